// round 4
// baseline (speedup 1.0000x reference)
#include <cuda_runtime.h>

// AdditiveAttention: out[b,q,v] = softmax_k( sum_h w_v[h]*tanh(q~[b,q,h]+k~[b,k,h]) ) @ V
// B=4, Q=256, K=1024, IN=256, H=128, V=256.

#define NEGV -1000000.0f

// Scratch (__device__ globals — no allocation allowed)
__device__ float g_wqt[256 * 128];       // W_q transposed [in][h]
__device__ float g_wkt[256 * 128];       // W_k transposed [in][h]
__device__ float g_qp[4 * 256 * 128];    // projected queries
__device__ float g_kp[4 * 1024 * 128];   // projected keys

__device__ __forceinline__ float tanh_apx(float x) {
    float y;
    asm("tanh.approx.f32 %0, %1;" : "=f"(y) : "f"(x));
    return y;
}

// ---------------------------------------------------------------------------
// K0: transpose W_q, W_k ([128,256] row-major -> [256,128]) for coalesced
// access in the projection kernel. 65536 threads total, writes coalesced.
// ---------------------------------------------------------------------------
__global__ void k_transpose(const float* __restrict__ Wq,
                            const float* __restrict__ Wk) {
    int idx = blockIdx.x * blockDim.x + threadIdx.x;  // 0..65535
    int m = idx >> 15;          // 0 = Wq, 1 = Wk
    int j = idx & 32767;        // 0..32767
    int i = j >> 7;             // input-feature index 0..255
    int h = j & 127;            // output-feature index 0..127
    const float* W = m ? Wk : Wq;
    float* Wt = m ? g_wkt : g_wqt;
    Wt[j] = W[h * 256 + i];
}

// ---------------------------------------------------------------------------
// K1: projections. Block = 16 rows x 128 outputs, 256 threads.
// Blocks [0,256): keys (4096 rows) -> g_kp. Blocks [256,320): queries -> g_qp.
// Thread t: h = t&127, owns 8 rows (half = t>>7). Wt reads coalesced, x rows
// staged in SMEM, broadcast LDS.128.
// ---------------------------------------------------------------------------
__global__ __launch_bounds__(256) void k_project(
    const float* __restrict__ queries, const float* __restrict__ keys) {
    __shared__ float xs[16 * 256];  // 16 KB
    int bx = blockIdx.x;
    const float* src;
    const float* Wt;
    float* dst;
    int r0;
    if (bx < 256) { src = keys;    Wt = g_wkt; dst = g_kp; r0 = bx * 16; }
    else          { src = queries; Wt = g_wqt; dst = g_qp; r0 = (bx - 256) * 16; }

    int t = threadIdx.x;
    const float4* s4 = (const float4*)(src + r0 * 256);
    float4* x4 = (float4*)xs;
    for (int idx = t; idx < 16 * 64; idx += 256) x4[idx] = s4[idx];
    __syncthreads();

    int h = t & 127;
    int half = t >> 7;
    float acc[8] = {0.f, 0.f, 0.f, 0.f, 0.f, 0.f, 0.f, 0.f};
    const float* xbase = xs + half * 8 * 256;

    #pragma unroll 4
    for (int i4 = 0; i4 < 64; ++i4) {
        int i = i4 * 4;
        float w0 = Wt[(i + 0) * 128 + h];
        float w1 = Wt[(i + 1) * 128 + h];
        float w2 = Wt[(i + 2) * 128 + h];
        float w3 = Wt[(i + 3) * 128 + h];
        #pragma unroll
        for (int r = 0; r < 8; ++r) {
            float4 xv = *(const float4*)(xbase + r * 256 + i);
            acc[r] = fmaf(w0, xv.x, acc[r]);
            acc[r] = fmaf(w1, xv.y, acc[r]);
            acc[r] = fmaf(w2, xv.z, acc[r]);
            acc[r] = fmaf(w3, xv.w, acc[r]);
        }
    }
    #pragma unroll
    for (int r = 0; r < 8; ++r)
        dst[(r0 + half * 8 + r) * 128 + h] = acc[r];
}

// ---------------------------------------------------------------------------
// K2: attention. Grid (32, 4): blockIdx.x = 8-query tile, blockIdx.y = batch.
// 256 threads = 8 warps; warp w owns query row q0+w.
// Phase A (scores): k~ staged in 64-row SMEM chunks; lane holds q,w_v for
//   h = lane+32j; per k: 4 tanh + butterfly-reduce. Chunks past vlen skipped.
// Phase B: warp-local masked softmax (row written/read by same warp).
// Phase C: attn@V, thread t owns output column v=t; k-loop bounded by vlen.
// Dynamic SMEM: ks 32KB + scores 32KB = 64KB.
// ---------------------------------------------------------------------------
__global__ __launch_bounds__(256) void k_attn(
    const float* __restrict__ values, const int* __restrict__ valid_lens,
    const float* __restrict__ w_v, float* __restrict__ out) {
    extern __shared__ float sm[];
    float* ks = sm;              // [64][128]
    float* ss = sm + 64 * 128;   // [8][1024]

    int b = blockIdx.y;
    int q0 = blockIdx.x * 8;
    int t = threadIdx.x, w = t >> 5, lane = t & 31;
    int vlen = valid_lens[b];

    float qreg[4], wv[4];
    #pragma unroll
    for (int j = 0; j < 4; ++j) {
        qreg[j] = g_qp[(b * 256 + q0 + w) * 128 + lane + 32 * j];
        wv[j] = w_v[lane + 32 * j];
    }

    // ---- Phase A: scores ----
    for (int kc = 0; kc < 16 && kc * 64 < vlen; ++kc) {
        __syncthreads();  // previous chunk's ks reads complete before overwrite
        const float4* kp4 = (const float4*)&g_kp[(b * 1024 + kc * 64) * 128];
        float4* ks4 = (float4*)ks;
        for (int idx = t; idx < 64 * 32; idx += 256) ks4[idx] = kp4[idx];
        __syncthreads();

        float* srow = &ss[w * 1024 + kc * 64];
        #pragma unroll 4
        for (int kk = 0; kk < 64; ++kk) {
            const float* kr = &ks[kk * 128];
            float p = 0.f;
            #pragma unroll
            for (int j = 0; j < 4; ++j) {
                float th = tanh_apx(qreg[j] + kr[lane + 32 * j]);
                p = fmaf(wv[j], th, p);
            }
            p += __shfl_xor_sync(0xffffffffu, p, 16);
            p += __shfl_xor_sync(0xffffffffu, p, 8);
            p += __shfl_xor_sync(0xffffffffu, p, 4);
            p += __shfl_xor_sync(0xffffffffu, p, 2);
            p += __shfl_xor_sync(0xffffffffu, p, 1);
            if (lane == 0) srow[kk] = p;
        }
    }
    __syncwarp();  // lane0's smem score writes visible to whole warp

    // ---- Phase B: masked softmax, warp-local on own row ----
    {
        float* row = &ss[w * 1024];
        float m = NEGV;
        for (int i = lane; i < 1024; i += 32) {
            float s = (i < vlen) ? row[i] : NEGV;
            m = fmaxf(m, s);
        }
        m = fmaxf(m, __shfl_xor_sync(0xffffffffu, m, 16));
        m = fmaxf(m, __shfl_xor_sync(0xffffffffu, m, 8));
        m = fmaxf(m, __shfl_xor_sync(0xffffffffu, m, 4));
        m = fmaxf(m, __shfl_xor_sync(0xffffffffu, m, 2));
        m = fmaxf(m, __shfl_xor_sync(0xffffffffu, m, 1));

        float sum = 0.f;
        for (int i = lane; i < 1024; i += 32) {
            float e = 0.f;
            if (i < vlen) e = __expf(row[i] - m);
            row[i] = e;  // zero for masked / never-computed region
            sum += e;
        }
        sum += __shfl_xor_sync(0xffffffffu, sum, 16);
        sum += __shfl_xor_sync(0xffffffffu, sum, 8);
        sum += __shfl_xor_sync(0xffffffffu, sum, 4);
        sum += __shfl_xor_sync(0xffffffffu, sum, 2);
        sum += __shfl_xor_sync(0xffffffffu, sum, 1);
        float inv = 1.f / sum;
        for (int i = lane; i < 1024; i += 32) row[i] *= inv;
    }
    __syncthreads();  // all rows of ss visible to all warps

    // ---- Phase C: out = attn @ V, thread owns v = t ----
    const float* V = values + b * 1024 * 256;
    float acc[8] = {0.f, 0.f, 0.f, 0.f, 0.f, 0.f, 0.f, 0.f};
    int ng = (vlen + 3) >> 2;  // attn is exactly 0 beyond vlen
    for (int g = 0; g < ng; ++g) {
        int k = g * 4;
        float4 a[8];
        #pragma unroll
        for (int qi = 0; qi < 8; ++qi)
            a[qi] = *(const float4*)&ss[qi * 1024 + k];
        #pragma unroll
        for (int dk = 0; dk < 4; ++dk) {
            float vv = V[(k + dk) * 256 + t];
            #pragma unroll
            for (int qi = 0; qi < 8; ++qi) {
                float av = (dk == 0) ? a[qi].x
                         : (dk == 1) ? a[qi].y
                         : (dk == 2) ? a[qi].z
                                     : a[qi].w;
                acc[qi] = fmaf(av, vv, acc[qi]);
            }
        }
    }
    #pragma unroll
    for (int qi = 0; qi < 8; ++qi)
        out[(b * 256 + q0 + qi) * 256 + t] = acc[qi];
}

// ---------------------------------------------------------------------------
extern "C" void kernel_launch(void* const* d_in, const int* in_sizes, int n_in,
                              void* d_out, int out_size) {
    const float* queries    = (const float*)d_in[0];  // [4,256,256]
    const float* keys       = (const float*)d_in[1];  // [4,1024,256]
    const float* values     = (const float*)d_in[2];  // [4,1024,256]
    const int*   valid_lens = (const int*)d_in[3];    // [4]
    const float* W_q        = (const float*)d_in[4];  // [128,256]
    const float* W_k        = (const float*)d_in[5];  // [128,256]
    const float* w_v        = (const float*)d_in[6];  // [128]
    float* out = (float*)d_out;                       // [4,256,256]

    cudaFuncSetAttribute(k_attn, cudaFuncAttributeMaxDynamicSharedMemorySize,
                         65536);

    k_transpose<<<256, 256>>>(W_q, W_k);
    k_project<<<320, 256>>>(queries, keys);
    k_attn<<<dim3(32, 4), 256, 65536>>>(values, valid_lens, w_v, out);
}

// round 5
// speedup vs baseline: 1.3285x; 1.3285x over previous
#include <cuda_runtime.h>

// AdditiveAttention: out[b,q,v] = softmax_k( sum_h w_v[h]*tanh(q~[b,q,h]+k~[b,k,h]) ) @ V
// B=4, Q=256, K=1024, IN=256, H=128, V=256.

// Scratch (__device__ globals — no allocation allowed)
__device__ float g_wqt[256 * 128];       // W_q transposed [in][h]
__device__ float g_wkt[256 * 128];       // W_k transposed [in][h]
__device__ float g_qp[4 * 256 * 128];    // projected queries
__device__ float g_kp[4 * 1024 * 128];   // projected keys

__device__ __forceinline__ float tanh_apx(float x) {
    float y;
    asm("tanh.approx.f32 %0, %1;" : "=f"(y) : "f"(x));
    return y;
}

// Packed fp32x2 FMA: d = a*b + d (element-wise on both 32-bit halves)
__device__ __forceinline__ void fma2(unsigned long long& d,
                                     unsigned long long a,
                                     unsigned long long b) {
    asm("fma.rn.f32x2 %0, %1, %2, %0;" : "+l"(d) : "l"(a), "l"(b));
}

// ---------------------------------------------------------------------------
// K0: transpose W_q, W_k ([128,256] -> [256,128]) for coalesced projection.
// ---------------------------------------------------------------------------
__global__ void k_transpose(const float* __restrict__ Wq,
                            const float* __restrict__ Wk) {
    int idx = blockIdx.x * blockDim.x + threadIdx.x;  // 0..65535
    int m = idx >> 15;
    int j = idx & 32767;
    int i = j >> 7;
    int h = j & 127;
    const float* W = m ? Wk : Wq;
    float* Wt = m ? g_wkt : g_wqt;
    Wt[j] = W[h * 256 + i];
}

// ---------------------------------------------------------------------------
// K1: projections. Block = 16 rows x 128 outputs, 256 threads.
// Blocks [0,256): keys -> g_kp. Blocks [256,320): queries -> g_qp.
// ---------------------------------------------------------------------------
__global__ __launch_bounds__(256) void k_project(
    const float* __restrict__ queries, const float* __restrict__ keys) {
    __shared__ float xs[16 * 256];
    int bx = blockIdx.x;
    const float* src;
    const float* Wt;
    float* dst;
    int r0;
    if (bx < 256) { src = keys;    Wt = g_wkt; dst = g_kp; r0 = bx * 16; }
    else          { src = queries; Wt = g_wqt; dst = g_qp; r0 = (bx - 256) * 16; }

    int t = threadIdx.x;
    const float4* s4 = (const float4*)(src + r0 * 256);
    float4* x4 = (float4*)xs;
    for (int idx = t; idx < 16 * 64; idx += 256) x4[idx] = s4[idx];
    __syncthreads();

    int h = t & 127;
    int half = t >> 7;
    float acc[8] = {0.f, 0.f, 0.f, 0.f, 0.f, 0.f, 0.f, 0.f};
    const float* xbase = xs + half * 8 * 256;

    #pragma unroll 4
    for (int i4 = 0; i4 < 64; ++i4) {
        int i = i4 * 4;
        float w0 = Wt[(i + 0) * 128 + h];
        float w1 = Wt[(i + 1) * 128 + h];
        float w2 = Wt[(i + 2) * 128 + h];
        float w3 = Wt[(i + 3) * 128 + h];
        #pragma unroll
        for (int r = 0; r < 8; ++r) {
            float4 xv = *(const float4*)(xbase + r * 256 + i);
            acc[r] = fmaf(w0, xv.x, acc[r]);
            acc[r] = fmaf(w1, xv.y, acc[r]);
            acc[r] = fmaf(w2, xv.z, acc[r]);
            acc[r] = fmaf(w3, xv.w, acc[r]);
        }
    }
    #pragma unroll
    for (int r = 0; r < 8; ++r)
        dst[(r0 + half * 8 + r) * 128 + h] = acc[r];
}

// ---------------------------------------------------------------------------
// K2: fused scores + softmax + attn@V. Grid (64, 4): x = 4-query tile, y = b.
// 256 threads. Per 64-k chunk:
//   Phase A: thread (q = t>>6, k = t&63) computes score via h-loop over
//            transposed SMEM k~ tile; e = expf(score) (no max pass needed:
//            |score| <= sum|w_v| ~ 9, exp can't overflow); e stored duplicated
//            {e,e} for packed Phase C; per-thread running rowsum.
//   prefetch next k~ chunk (overlaps with Phase C)
//   Phase C: thread owns 2 v-cols x 2 q-rows, packed f32x2 FMAs with V.
// Final: out = acc / rowsum.
// SMEM: ksT[128][65] + qwv[4][128][2] + ebuf[4][64][2] + wsum[8] ~ 39.5 KB
// -> 2 blocks/SM; 256 blocks all resident in one wave -> A/C pipe overlap.
// ---------------------------------------------------------------------------
#define SMEM_ATTN ((128 * 65 + 4 * 128 * 2 + 4 * 64 * 2 + 8) * 4)

__global__ __launch_bounds__(256) void k_attn2(
    const float* __restrict__ values, const int* __restrict__ valid_lens,
    const float* __restrict__ w_v, float* __restrict__ out) {
    extern __shared__ float sm[];
    float* ksT  = sm;                        // [128][65]
    float* qwv  = sm + 128 * 65;             // [4][128][2] = {q~, w_v}
    float* ebuf = qwv + 4 * 128 * 2;         // [4][64][2]  = {e, e}
    float* wsum = ebuf + 4 * 64 * 2;         // [8]

    int b = blockIdx.y;
    int q0 = blockIdx.x * 4;
    int t = threadIdx.x;
    int vlen = valid_lens[b];
    int nc = min(16, (vlen + 63) >> 6);

    // Init: interleaved (q~[q][h], w_v[h]) pairs
    for (int i = t; i < 512; i += 256) {
        qwv[i * 2]     = g_qp[(b * 256 + q0) * 128 + i];
        qwv[i * 2 + 1] = w_v[i & 127];
    }

    // Load k~ chunk 0, transposed with pad-65 (conflict-free ld & st)
    const float* kpB = g_kp + b * 1024 * 128;
    #pragma unroll
    for (int n = 0; n < 32; ++n) {
        int i = t + n * 256;
        int h = i & 127, kr = i >> 7;
        ksT[h * 65 + kr] = kpB[kr * 128 + h];
    }
    __syncthreads();

    // Phase A identity: one score per thread
    int qa = t >> 6;                 // 0..3
    int ka = t & 63;                 // 0..63
    const float* qw = qwv + qa * 256;
    float lsum = 0.f;

    // Phase C identity: 2 v-cols x 2 q-rows per thread
    int qb = (t >> 7) * 2;           // 0 or 2
    int vp = (t & 127) * 2;          // even v column
    unsigned long long acc0 = 0ull, acc1 = 0ull;  // f32x2 {0,0}
    const float* Vb = values + b * 1024 * 256;

    for (int c = 0; c < nc; ++c) {
        // ---- Phase A: score + exp ----
        float s0 = 0.f, s1 = 0.f;
        #pragma unroll 8
        for (int h = 0; h < 128; h += 2) {
            float2 a0 = *(const float2*)&qw[h * 2];        // broadcast LDS.64
            float2 a1 = *(const float2*)&qw[h * 2 + 2];
            float x0 = a0.x + ksT[h * 65 + ka];
            float x1 = a1.x + ksT[(h + 1) * 65 + ka];
            s0 = fmaf(a0.y, tanh_apx(x0), s0);
            s1 = fmaf(a1.y, tanh_apx(x1), s1);
        }
        float e = 0.f;
        if (c * 64 + ka < vlen) e = __expf(s0 + s1);
        *(float2*)&ebuf[(qa * 64 + ka) * 2] = make_float2(e, e);
        lsum += e;
        __syncthreads();

        // ---- prefetch next k~ chunk (ksT free: Phase A done) ----
        if (c + 1 < nc) {
            const float* src = kpB + (c + 1) * 64 * 128;
            #pragma unroll
            for (int n = 0; n < 32; ++n) {
                int i = t + n * 256;
                int h = i & 127, kr = i >> 7;
                ksT[h * 65 + kr] = src[kr * 128 + h];
            }
        }

        // ---- Phase C: acc += e * V (packed f32x2) ----
        const float* Vc = Vb + c * 64 * 256;
        #pragma unroll 4
        for (int kk = 0; kk < 64; ++kk) {
            unsigned long long vv =
                *(const unsigned long long*)&Vc[kk * 256 + vp];
            unsigned long long e0 =
                *(const unsigned long long*)&ebuf[((qb + 0) * 64 + kk) * 2];
            unsigned long long e1 =
                *(const unsigned long long*)&ebuf[((qb + 1) * 64 + kk) * 2];
            fma2(acc0, e0, vv);
            fma2(acc1, e1, vv);
        }
        __syncthreads();
    }

    // Row sums: warp w covers fixed q = w>>1, distinct k slices
    lsum += __shfl_xor_sync(0xffffffffu, lsum, 16);
    lsum += __shfl_xor_sync(0xffffffffu, lsum, 8);
    lsum += __shfl_xor_sync(0xffffffffu, lsum, 4);
    lsum += __shfl_xor_sync(0xffffffffu, lsum, 2);
    lsum += __shfl_xor_sync(0xffffffffu, lsum, 1);
    int lane = t & 31, w = t >> 5;
    if (lane == 0) wsum[w] = lsum;
    __syncthreads();

    float inv0 = 1.f / (wsum[(qb + 0) * 2] + wsum[(qb + 0) * 2 + 1]);
    float inv1 = 1.f / (wsum[(qb + 1) * 2] + wsum[(qb + 1) * 2 + 1]);

    float2 a0 = *(float2*)&acc0;
    float2 a1 = *(float2*)&acc1;
    float2 o0 = make_float2(a0.x * inv0, a0.y * inv0);
    float2 o1 = make_float2(a1.x * inv1, a1.y * inv1);
    *(float2*)&out[(b * 256 + q0 + qb + 0) * 256 + vp] = o0;
    *(float2*)&out[(b * 256 + q0 + qb + 1) * 256 + vp] = o1;
}

// ---------------------------------------------------------------------------
extern "C" void kernel_launch(void* const* d_in, const int* in_sizes, int n_in,
                              void* d_out, int out_size) {
    const float* queries    = (const float*)d_in[0];  // [4,256,256]
    const float* keys       = (const float*)d_in[1];  // [4,1024,256]
    const float* values     = (const float*)d_in[2];  // [4,1024,256]
    const int*   valid_lens = (const int*)d_in[3];    // [4]
    const float* W_q        = (const float*)d_in[4];  // [128,256]
    const float* W_k        = (const float*)d_in[5];  // [128,256]
    const float* w_v        = (const float*)d_in[6];  // [128]
    float* out = (float*)d_out;                       // [4,256,256]

    cudaFuncSetAttribute(k_attn2, cudaFuncAttributeMaxDynamicSharedMemorySize,
                         SMEM_ATTN);

    k_transpose<<<256, 256>>>(W_q, W_k);
    k_project<<<320, 256>>>(queries, keys);
    k_attn2<<<dim3(64, 4), 256, SMEM_ATTN>>>(values, valid_lens, w_v, out);
}

// round 8
// speedup vs baseline: 1.8958x; 1.4271x over previous
#include <cuda_runtime.h>

// AdditiveAttention: out[b,q,v] = softmax_k( sum_h w_v[h]*tanh(q~[b,q,h]+k~[b,k,h]) ) @ V
// B=4, Q=256, K=1024, IN=256, H=128, V=256.

// Scratch (__device__ globals — no allocation allowed)
__device__ float g_wqt[256 * 128];            // W_q^T [in][h]
__device__ float g_wkt[256 * 128];            // W_k^T [in][h]
__device__ float g_qp[4 * 256 * 128];         // projected queries
__device__ float g_kp[4 * 1024 * 128];        // projected keys
__device__ float g_pacc[16 * 256 * 256];      // partial acc [b*4+kq][q][v]
__device__ float g_psum[16 * 256];            // partial exp-sums [b*4+kq][q]

__device__ __forceinline__ float tanh_apx(float x) {
    float y;
    asm("tanh.approx.f32 %0, %1;" : "=f"(y) : "f"(x));
    return y;
}

__device__ __forceinline__ void fma2(unsigned long long& d,
                                     unsigned long long a,
                                     unsigned long long b) {
    asm("fma.rn.f32x2 %0, %1, %2, %0;" : "+l"(d) : "l"(a), "l"(b));
}

// ---------------------------------------------------------------------------
// K0: tiled transpose of W_q, W_k ([128,256] -> [256,128]), coalesced both
// ways via 32x33 SMEM tile. 64 blocks x 256 threads.
// ---------------------------------------------------------------------------
__global__ __launch_bounds__(256) void k_transpose(
    const float* __restrict__ Wq, const float* __restrict__ Wk) {
    __shared__ float tile[32][33];
    int bid = blockIdx.x;
    int m = bid >> 5;          // 0 = Wq, 1 = Wk
    int tb = bid & 31;
    int hb = tb >> 3;          // 0..3  (h tile)
    int ib = tb & 7;           // 0..7  (i tile)
    const float* W = m ? Wk : Wq;
    float* Wt = m ? g_wkt : g_wqt;

    int t = threadIdx.x;
    int c = t & 31, r0 = t >> 5;   // 32 cols x 8 row-groups
    #pragma unroll
    for (int rr = 0; rr < 4; ++rr) {
        int r = r0 * 4 + rr;
        tile[r][c] = W[(hb * 32 + r) * 256 + ib * 32 + c];  // coalesced read
    }
    __syncthreads();
    #pragma unroll
    for (int rr = 0; rr < 4; ++rr) {
        int r = r0 * 4 + rr;
        Wt[(ib * 32 + r) * 128 + hb * 32 + c] = tile[c][r];  // coalesced write
    }
}

// ---------------------------------------------------------------------------
// K1: projections. Block = 16 rows x 128 outputs, 256 threads.
// Blocks [0,256): keys -> g_kp. Blocks [256,320): queries -> g_qp.
// ---------------------------------------------------------------------------
__global__ __launch_bounds__(256) void k_project(
    const float* __restrict__ queries, const float* __restrict__ keys) {
    __shared__ float xs[16 * 256];
    int bx = blockIdx.x;
    const float* src;
    const float* Wt;
    float* dst;
    int r0;
    if (bx < 256) { src = keys;    Wt = g_wkt; dst = g_kp; r0 = bx * 16; }
    else          { src = queries; Wt = g_wqt; dst = g_qp; r0 = (bx - 256) * 16; }

    int t = threadIdx.x;
    const float4* s4 = (const float4*)(src + r0 * 256);
    float4* x4 = (float4*)xs;
    for (int idx = t; idx < 16 * 64; idx += 256) x4[idx] = s4[idx];
    __syncthreads();

    int h = t & 127;
    int half = t >> 7;
    float acc[8] = {0.f, 0.f, 0.f, 0.f, 0.f, 0.f, 0.f, 0.f};
    const float* xbase = xs + half * 8 * 256;

    #pragma unroll 4
    for (int i4 = 0; i4 < 64; ++i4) {
        int i = i4 * 4;
        float w0 = Wt[(i + 0) * 128 + h];
        float w1 = Wt[(i + 1) * 128 + h];
        float w2 = Wt[(i + 2) * 128 + h];
        float w3 = Wt[(i + 3) * 128 + h];
        #pragma unroll
        for (int r = 0; r < 8; ++r) {
            float4 xv = *(const float4*)(xbase + r * 256 + i);
            acc[r] = fmaf(w0, xv.x, acc[r]);
            acc[r] = fmaf(w1, xv.y, acc[r]);
            acc[r] = fmaf(w2, xv.z, acc[r]);
            acc[r] = fmaf(w3, xv.w, acc[r]);
        }
    }
    #pragma unroll
    for (int r = 0; r < 8; ++r)
        dst[(r0 + half * 8 + r) * 128 + h] = acc[r];
}

// ---------------------------------------------------------------------------
// K2: split-K fused scores+exp+attnV partials.
// 1024 blocks: bid -> b = bid&3, kq = (bid>>2)&3, qt = bid>>4.
// Block covers 4 queries (qt*4..) x 256 keys (kq*256..) as <=2 chunks of 128.
// Blocks beyond vlen exit immediately -> work-stealing balances batches.
// Per chunk:
//   Phase A: thread (q = t>>6, k in {ka, ka+64}); h-loop over ks[k][129] SMEM
//            (pad-129: conflict-free), qwv interleaved broadcast LDS.64.
//            e = expf(score) (bounded: |score| <= sum|w_v| ~ 9), no max pass.
//   Phase C: thread (q = t>>6, 4 v-cols); packed f32x2 FMA with float4 V;
//            next chunk prefetched into ks first (C doesn't read ks).
// Outputs: g_pacc (unnormalized), g_psum. SMEM ~74.3KB -> 2 blocks/SM.
// ---------------------------------------------------------------------------
#define SMEM_ATTN ((128 * 129 + 1024 + 1024 + 8) * 4)

__global__ __launch_bounds__(256) void k_attn3(
    const float* __restrict__ values, const int* __restrict__ valid_lens,
    const float* __restrict__ w_v) {
    extern __shared__ float sm[];
    float* ks   = sm;                    // [128][129]
    float* qwv  = sm + 128 * 129;        // [4][128][2] = {q~, w_v}
    float* ebuf = qwv + 1024;            // [4][128][2] = {e, e}
    float* wsum = ebuf + 1024;           // [8]

    int bid = blockIdx.x;
    int b = bid & 3;
    int kq = (bid >> 2) & 3;
    int qt = bid >> 4;
    int vlen = valid_lens[b];
    int k0 = kq * 256;
    if (k0 >= vlen) return;
    int nch = (vlen - k0 > 128) ? 2 : 1;

    int t = threadIdx.x;
    int q0 = qt * 4;

    // qwv: interleaved (q~[q][h], w_v[h])
    for (int i = t; i < 512; i += 256) {
        qwv[i * 2]     = g_qp[(b * 256 + q0) * 128 + i];
        qwv[i * 2 + 1] = w_v[i & 127];
    }

    // load k~ chunk 0: ks[k][h], row stride 129 (odd -> conflict-free)
    const float* kpB = g_kp + (b * 1024 + k0) * 128;
    #pragma unroll 8
    for (int n = 0; n < 64; ++n) {
        int i = t + n * 256;
        int h = i & 127, kr = i >> 7;
        ks[kr * 129 + h] = kpB[i];
    }
    __syncthreads();

    int q = t >> 6;                  // warp-uniform
    int ka = t & 63;
    const float* qw = qwv + q * 256;
    const float* kr0 = ks + ka * 129;
    const float* kr1 = ks + (ka + 64) * 129;
    float lsum = 0.f;

    int vp = (t & 63) * 4;           // Phase C: 4 v-cols
    unsigned long long acc0 = 0ull, acc1 = 0ull;
    const float* Vb = values + (b * 1024 + k0) * 256;

    for (int c = 0; c < nch; ++c) {
        // ---- Phase A ----
        float s0 = 0.f, s1 = 0.f;
        #pragma unroll 8
        for (int h = 0; h < 128; ++h) {
            float2 a = *(const float2*)&qw[h * 2];   // broadcast
            float x0 = a.x + kr0[h];
            float x1 = a.x + kr1[h];
            s0 = fmaf(a.y, tanh_apx(x0), s0);
            s1 = fmaf(a.y, tanh_apx(x1), s1);
        }
        int kg = k0 + c * 128 + ka;
        float e0 = (kg < vlen)      ? __expf(s0) : 0.f;
        float e1 = (kg + 64 < vlen) ? __expf(s1) : 0.f;
        *(float2*)&ebuf[(q * 128 + ka) * 2]      = make_float2(e0, e0);
        *(float2*)&ebuf[(q * 128 + ka + 64) * 2] = make_float2(e1, e1);
        lsum += e0 + e1;
        __syncthreads();   // ebuf visible; ks reads done

        // ---- prefetch next chunk (Phase C doesn't read ks) ----
        if (c + 1 < nch) {
            const float* src = kpB + 128 * 128;
            #pragma unroll 8
            for (int n = 0; n < 64; ++n) {
                int i = t + n * 256;
                int h = i & 127, krr = i >> 7;
                ks[krr * 129 + h] = src[i];
            }
        }

        // ---- Phase C: acc += e * V ----
        const float* Vc = Vb + c * 128 * 256;
        const float* eb = ebuf + q * 128 * 2;
        #pragma unroll 4
        for (int kk = 0; kk < 128; ++kk) {
            float4 vv = *(const float4*)&Vc[kk * 256 + vp];
            unsigned long long ee = *(const unsigned long long*)&eb[kk * 2];
            unsigned long long v01 = *(unsigned long long*)&vv.x;
            unsigned long long v23 = *(unsigned long long*)&vv.z;
            fma2(acc0, ee, v01);
            fma2(acc1, ee, v23);
        }
        __syncthreads();   // prefetch done; ebuf reads done
    }

    // per-q exp sums: q is warp-uniform; warps 2q, 2q+1 cover q
    lsum += __shfl_xor_sync(0xffffffffu, lsum, 16);
    lsum += __shfl_xor_sync(0xffffffffu, lsum, 8);
    lsum += __shfl_xor_sync(0xffffffffu, lsum, 4);
    lsum += __shfl_xor_sync(0xffffffffu, lsum, 2);
    lsum += __shfl_xor_sync(0xffffffffu, lsum, 1);
    int lane = t & 31, w = t >> 5;
    if (lane == 0) wsum[w] = lsum;
    __syncthreads();
    if (t < 4)
        g_psum[(b * 4 + kq) * 256 + q0 + t] = wsum[2 * t] + wsum[2 * t + 1];

    // partial acc write (unnormalized)
    float* pa = &g_pacc[(((b * 4 + kq) * 256) + q0 + q) * 256 + vp];
    float4 o;
    o.x = ((float2*)&acc0)->x; o.y = ((float2*)&acc0)->y;
    o.z = ((float2*)&acc1)->x; o.w = ((float2*)&acc1)->y;
    *(float4*)pa = o;
}

// ---------------------------------------------------------------------------
// K3: combine partials. 256 blocks: (b = bid>>6, qt = bid&63), thread v = t.
// Only quarters p < ceil(vlen/256) were written; sum those and normalize.
// ---------------------------------------------------------------------------
__global__ __launch_bounds__(256) void k_combine(
    const int* __restrict__ valid_lens, float* __restrict__ out) {
    int bid = blockIdx.x;
    int b = bid >> 6;
    int qt = bid & 63;
    int t = threadIdx.x;
    int vlen = valid_lens[b];
    int np = (vlen + 255) >> 8;   // 1..4

    #pragma unroll
    for (int qi = 0; qi < 4; ++qi) {
        int q = qt * 4 + qi;
        float a = 0.f, s = 0.f;
        for (int p = 0; p < np; ++p) {
            a += g_pacc[((b * 4 + p) * 256 + q) * 256 + t];
            s += g_psum[(b * 4 + p) * 256 + q];
        }
        out[(b * 256 + q) * 256 + t] = a / s;
    }
}

// ---------------------------------------------------------------------------
extern "C" void kernel_launch(void* const* d_in, const int* in_sizes, int n_in,
                              void* d_out, int out_size) {
    const float* queries    = (const float*)d_in[0];  // [4,256,256]
    const float* keys       = (const float*)d_in[1];  // [4,1024,256]
    const float* values     = (const float*)d_in[2];  // [4,1024,256]
    const int*   valid_lens = (const int*)d_in[3];    // [4]
    const float* W_q        = (const float*)d_in[4];  // [128,256]
    const float* W_k        = (const float*)d_in[5];  // [128,256]
    const float* w_v        = (const float*)d_in[6];  // [128]
    float* out = (float*)d_out;                       // [4,256,256]

    cudaFuncSetAttribute(k_attn3, cudaFuncAttributeMaxDynamicSharedMemorySize,
                         SMEM_ATTN);

    k_transpose<<<64, 256>>>(W_q, W_k);
    k_project<<<320, 256>>>(queries, keys);
    k_attn3<<<1024, 256, SMEM_ATTN>>>(values, valid_lens, w_v);
    k_combine<<<256, 256>>>(valid_lens, out);
}

// round 9
// speedup vs baseline: 2.1475x; 1.1327x over previous
#include <cuda_runtime.h>
#include <cstdint>

// AdditiveAttention: out[b,q,v] = softmax_k( sum_h w_v[h]*tanh(q~[b,q,h]+k~[b,k,h]) ) @ V
// B=4, Q=256, K=1024, IN=256, H=128, V=256.

typedef unsigned long long ull;

// Scratch (__device__ globals — no allocation allowed)
__device__ float g_wqt[256 * 128];            // W_q^T [in][h]
__device__ float g_wkt[256 * 128];            // W_k^T [in][h]
__device__ float g_qp[4 * 256 * 128];         // projected queries
__device__ float g_kp[4 * 1024 * 128];        // projected keys
__device__ float g_pacc[16 * 256 * 256];      // partial acc [b*4+kq][q][v]
__device__ float g_psum[16 * 256];            // partial exp-sums [b*4+kq][q]

__device__ __forceinline__ float tanh_apx(float x) {
    float y;
    asm("tanh.approx.f32 %0, %1;" : "=f"(y) : "f"(x));
    return y;
}

__device__ __forceinline__ void fma2(ull& d, ull a, ull b) {
    asm("fma.rn.f32x2 %0, %1, %2, %0;" : "+l"(d) : "l"(a), "l"(b));
}

__device__ __forceinline__ ull pack2(float x) {
    ull r;
    asm("mov.b64 %0, {%1, %1};" : "=l"(r) : "f"(x));
    return r;
}

__device__ __forceinline__ void ldgsts16(uint32_t saddr, const void* g) {
    asm volatile("cp.async.cg.shared.global [%0], [%1], 16;"
                 :: "r"(saddr), "l"(g));
}
__device__ __forceinline__ void cp_commit() {
    asm volatile("cp.async.commit_group;" ::: "memory");
}
__device__ __forceinline__ void cp_wait0() {
    asm volatile("cp.async.wait_group 0;" ::: "memory");
}

// ---------------------------------------------------------------------------
// K0: tiled transpose of W_q, W_k ([128,256] -> [256,128]).
// ---------------------------------------------------------------------------
__global__ __launch_bounds__(256) void k_transpose(
    const float* __restrict__ Wq, const float* __restrict__ Wk) {
    __shared__ float tile[32][33];
    int bid = blockIdx.x;
    int m = bid >> 5;
    int tb = bid & 31;
    int hb = tb >> 3;
    int ib = tb & 7;
    const float* W = m ? Wk : Wq;
    float* Wt = m ? g_wkt : g_wqt;

    int t = threadIdx.x;
    int c = t & 31, r0 = t >> 5;
    #pragma unroll
    for (int rr = 0; rr < 4; ++rr) {
        int r = r0 * 4 + rr;
        tile[r][c] = W[(hb * 32 + r) * 256 + ib * 32 + c];
    }
    __syncthreads();
    #pragma unroll
    for (int rr = 0; rr < 4; ++rr) {
        int r = r0 * 4 + rr;
        Wt[(ib * 32 + r) * 128 + hb * 32 + c] = tile[c][r];
    }
}

// ---------------------------------------------------------------------------
// K1: projections with packed f32x2 FMA over row-pairs.
// Block = 16 rows x 128 h, 256 threads. Blocks [0,256): keys; [256,320): queries.
// xs staged TRANSPOSED as float2 row-pairs: xs2[i*9 + p] = {x[2p][i], x[2p+1][i]}.
// Thread: h = t&127, half = t>>7 -> pairs p = half*4 .. half*4+3.
// Inner per i: 1 LDG w (coalesced) + 1 pack + 4 (LDS.64 + fma2) -> 8 FMAs.
// ---------------------------------------------------------------------------
__global__ __launch_bounds__(256) void k_project(
    const float* __restrict__ queries, const float* __restrict__ keys) {
    __shared__ float2 xs2[256 * 9];   // 18 KB
    int bx = blockIdx.x;
    const float* src;
    const float* Wt;
    float* dst;
    int r0;
    if (bx < 256) { src = keys;    Wt = g_wkt; dst = g_kp; r0 = bx * 16; }
    else          { src = queries; Wt = g_wqt; dst = g_qp; r0 = (bx - 256) * 16; }

    int t = threadIdx.x;
    // stage transposed: element (row r, feat i) -> xs2[i*9 + r/2] half r&1
    float* xsf = (float*)xs2;
    const float* s0 = src + r0 * 256;
    #pragma unroll 4
    for (int n = 0; n < 16; ++n) {
        int idx = t + n * 256;          // 4096 elements
        int r = idx >> 8, i = idx & 255;
        xsf[i * 18 + r] = s0[r * 256 + i];
    }
    __syncthreads();

    int h = t & 127;
    int half = t >> 7;                  // 0: rows 0-7, 1: rows 8-15
    const float2* xp = xs2 + half * 4;
    ull acc0 = 0ull, acc1 = 0ull, acc2 = 0ull, acc3 = 0ull;

    #pragma unroll 4
    for (int i = 0; i < 256; ++i) {
        float w = Wt[i * 128 + h];
        ull w2 = pack2(w);
        const float2* xi = xp + i * 9;
        fma2(acc0, *(const ull*)&xi[0], w2);
        fma2(acc1, *(const ull*)&xi[1], w2);
        fma2(acc2, *(const ull*)&xi[2], w2);
        fma2(acc3, *(const ull*)&xi[3], w2);
    }

    int rb = r0 + half * 8;
    float2 a;
    a = *(float2*)&acc0; dst[(rb + 0) * 128 + h] = a.x; dst[(rb + 1) * 128 + h] = a.y;
    a = *(float2*)&acc1; dst[(rb + 2) * 128 + h] = a.x; dst[(rb + 3) * 128 + h] = a.y;
    a = *(float2*)&acc2; dst[(rb + 4) * 128 + h] = a.x; dst[(rb + 5) * 128 + h] = a.y;
    a = *(float2*)&acc3; dst[(rb + 6) * 128 + h] = a.x; dst[(rb + 7) * 128 + h] = a.y;
}

// ---------------------------------------------------------------------------
// K2: split-K fused attn, software-pipelined.
// 1024 blocks: b = bid&3, kq = (bid>>2)&3, qt = bid>>4. 4 q x 256 k / block,
// processed as <=4 chunks of 64 k. Blocks past vlen exit.
// ks double-buffered via cp.async, swizzled float4 layout:
//   ks4[buf*2048 + k*32 + ((h4+k)&31)]  (16B-aligned stores, conflict-free LDS.128)
// Mainloop chunk c (c>=1): Phase A(c) fused with Phase C(c-1) in one loop:
//   per j<32: A: LDS.128 ks/q/wv + 4 (add,tanh,fma);  C: kk=2j,2j+1:
//   2 LDG.128 V + 2 LDS.64 e + 4 fma2.  ~27 issues / 4 MUFU < 32-cyc budget.
// e stored duplicated {e,e} in double-buffered ebuf. One barrier per chunk.
// SMEM 72224 B -> 3 blocks/SM.
// ---------------------------------------------------------------------------
#define SMEM_ATTN (65536 + 2048 + 512 + 4096 + 32)

__global__ __launch_bounds__(256, 3) void k_attn4(
    const float* __restrict__ values, const int* __restrict__ valid_lens,
    const float* __restrict__ w_v) {
    extern __shared__ float sm[];
    float4* ks4  = (float4*)sm;                      // [2][64*32] float4
    float*  qs   = sm + 16384;                       // [4][128]
    float*  wvs  = qs + 512;                         // [128]
    float2* eb2  = (float2*)(wvs + 128);             // [2][256] = {e,e}
    float*  wsum = (float*)(eb2 + 512);              // [8]

    int bid = blockIdx.x;
    int b = bid & 3;
    int kq = (bid >> 2) & 3;
    int qt = bid >> 4;
    int vlen = valid_lens[b];
    int k0 = kq * 256;
    if (k0 >= vlen) return;
    int nch = min(4, (vlen - k0 + 63) >> 6);

    int t = threadIdx.x;
    int q0 = qt * 4;
    int qa = t >> 6;                 // warp-uniform q (0..3)
    int ka = t & 63;                 // A: key index within chunk
    int vp = (t & 63) * 4;           // C: 4 v-cols

    const float4* kp4 = (const float4*)(g_kp + (b * 1024 + k0) * 128);
    const float* Vb = values + (b * 1024 + k0) * 256;
    uint32_t ksaddr = (uint32_t)__cvta_generic_to_shared(ks4);

    // ---- issue chunk 0 copy ----
    {
        #pragma unroll
        for (int n = 0; n < 8; ++n) {
            int idx = t + n * 256;                // 0..2047
            int kk = idx >> 5, h4 = idx & 31;
            uint32_t d = ksaddr + (uint32_t)((kk * 32 + ((h4 + kk) & 31)) * 16);
            ldgsts16(d, kp4 + kk * 32 + h4);
        }
        cp_commit();
    }

    // ---- load qs, wvs while copy flies ----
    for (int i = t; i < 512; i += 256)
        qs[i] = g_qp[(b * 256 + q0) * 128 + i];
    if (t < 128) wvs[t] = w_v[t];
    cp_wait0();

    ull acc0 = 0ull, acc1 = 0ull;
    float lsum = 0.f;
    const float* qrow = qs + qa * 128;

    for (int c = 0; c < nch; ++c) {
        __syncthreads();   // copies of chunk c done (all threads); ebuf(c-1) visible

        // issue chunk c+1 into the other buffer (safe: all threads past A(c-1))
        if (c + 1 < nch) {
            int buf = (c + 1) & 1;
            const float4* srcc = kp4 + (c + 1) * 2048;
            #pragma unroll
            for (int n = 0; n < 8; ++n) {
                int idx = t + n * 256;
                int kk = idx >> 5, h4 = idx & 31;
                uint32_t d = ksaddr +
                    (uint32_t)((buf * 2048 + kk * 32 + ((h4 + kk) & 31)) * 16);
                ldgsts16(d, srcc + kk * 32 + h4);
            }
            cp_commit();
        }

        const float4* ksb = ks4 + (c & 1) * 2048 + ka * 32;
        float s = 0.f;

        if (c == 0) {
            // A-only
            #pragma unroll 8
            for (int j = 0; j < 32; ++j) {
                float4 kv = ksb[(j + ka) & 31];
                float4 q4 = *(const float4*)&qrow[j * 4];
                float4 w4 = *(const float4*)&wvs[j * 4];
                s = fmaf(w4.x, tanh_apx(q4.x + kv.x), s);
                s = fmaf(w4.y, tanh_apx(q4.y + kv.y), s);
                s = fmaf(w4.z, tanh_apx(q4.z + kv.z), s);
                s = fmaf(w4.w, tanh_apx(q4.w + kv.w), s);
            }
        } else {
            // fused A(c) + C(c-1)
            const float2* eb = eb2 + ((c & 1) ^ 1) * 256 + qa * 64;
            const float* Vp = Vb + (c - 1) * 64 * 256 + vp;
            #pragma unroll 4
            for (int j = 0; j < 32; ++j) {
                float4 kv = ksb[(j + ka) & 31];
                float4 q4 = *(const float4*)&qrow[j * 4];
                float4 w4 = *(const float4*)&wvs[j * 4];
                s = fmaf(w4.x, tanh_apx(q4.x + kv.x), s);
                s = fmaf(w4.y, tanh_apx(q4.y + kv.y), s);
                s = fmaf(w4.z, tanh_apx(q4.z + kv.z), s);
                s = fmaf(w4.w, tanh_apx(q4.w + kv.w), s);
                float2 e0 = eb[2 * j];
                float2 e1 = eb[2 * j + 1];
                float4 v0 = *(const float4*)&Vp[(2 * j) * 256];
                float4 v1 = *(const float4*)&Vp[(2 * j + 1) * 256];
                fma2(acc0, *(ull*)&e0, *(ull*)&v0.x);
                fma2(acc1, *(ull*)&e0, *(ull*)&v0.z);
                fma2(acc0, *(ull*)&e1, *(ull*)&v1.x);
                fma2(acc1, *(ull*)&e1, *(ull*)&v1.z);
            }
        }

        // exp + store e (duplicated), masked
        int kg = k0 + c * 64 + ka;
        float e = (kg < vlen) ? __expf(s) : 0.f;
        eb2[(c & 1) * 256 + qa * 64 + ka] = make_float2(e, e);
        lsum += e;
        if (c + 1 < nch) cp_wait0();   // own copies for c+1 done before next sync
    }

    // ---- epilogue: C(nch-1) ----
    __syncthreads();
    {
        const float2* eb = eb2 + ((nch - 1) & 1) * 256 + qa * 64;
        const float* Vp = Vb + (nch - 1) * 64 * 256 + vp;
        #pragma unroll 4
        for (int kk = 0; kk < 64; ++kk) {
            float2 e0 = eb[kk];
            float4 v0 = *(const float4*)&Vp[kk * 256];
            fma2(acc0, *(ull*)&e0, *(ull*)&v0.x);
            fma2(acc1, *(ull*)&e0, *(ull*)&v0.z);
        }
    }

    // per-q exp sums: warps 2q, 2q+1 cover q
    lsum += __shfl_xor_sync(0xffffffffu, lsum, 16);
    lsum += __shfl_xor_sync(0xffffffffu, lsum, 8);
    lsum += __shfl_xor_sync(0xffffffffu, lsum, 4);
    lsum += __shfl_xor_sync(0xffffffffu, lsum, 2);
    lsum += __shfl_xor_sync(0xffffffffu, lsum, 1);
    int lane = t & 31, w = t >> 5;
    if (lane == 0) wsum[w] = lsum;
    __syncthreads();
    if (t < 4)
        g_psum[(b * 4 + kq) * 256 + q0 + t] = wsum[2 * t] + wsum[2 * t + 1];

    float* pa = &g_pacc[(((b * 4 + kq) * 256) + q0 + qa) * 256 + vp];
    float4 o;
    o.x = ((float2*)&acc0)->x; o.y = ((float2*)&acc0)->y;
    o.z = ((float2*)&acc1)->x; o.w = ((float2*)&acc1)->y;
    *(float4*)pa = o;
}

// ---------------------------------------------------------------------------
// K3: combine partials. 1024 blocks: b = bid>>8, q = bid&255; thread v = t.
// All loads issued upfront (predicated) for MLP; uniform psum loads broadcast.
// ---------------------------------------------------------------------------
__global__ __launch_bounds__(256) void k_combine(
    const int* __restrict__ valid_lens, float* __restrict__ out) {
    int bid = blockIdx.x;
    int b = bid >> 8;
    int q = bid & 255;
    int t = threadIdx.x;
    int vlen = valid_lens[b];
    int np = (vlen + 255) >> 8;   // 1..4

    float a0 = g_pacc[((b * 4 + 0) * 256 + q) * 256 + t];
    float s0 = g_psum[(b * 4 + 0) * 256 + q];
    float a1 = (np > 1) ? g_pacc[((b * 4 + 1) * 256 + q) * 256 + t] : 0.f;
    float s1 = (np > 1) ? g_psum[(b * 4 + 1) * 256 + q] : 0.f;
    float a2 = (np > 2) ? g_pacc[((b * 4 + 2) * 256 + q) * 256 + t] : 0.f;
    float s2 = (np > 2) ? g_psum[(b * 4 + 2) * 256 + q] : 0.f;
    float a3 = (np > 3) ? g_pacc[((b * 4 + 3) * 256 + q) * 256 + t] : 0.f;
    float s3 = (np > 3) ? g_psum[(b * 4 + 3) * 256 + q] : 0.f;

    out[(b * 256 + q) * 256 + t] = ((a0 + a1) + (a2 + a3)) /
                                   ((s0 + s1) + (s2 + s3));
}

// ---------------------------------------------------------------------------
extern "C" void kernel_launch(void* const* d_in, const int* in_sizes, int n_in,
                              void* d_out, int out_size) {
    const float* queries    = (const float*)d_in[0];  // [4,256,256]
    const float* keys       = (const float*)d_in[1];  // [4,1024,256]
    const float* values     = (const float*)d_in[2];  // [4,1024,256]
    const int*   valid_lens = (const int*)d_in[3];    // [4]
    const float* W_q        = (const float*)d_in[4];  // [128,256]
    const float* W_k        = (const float*)d_in[5];  // [128,256]
    const float* w_v        = (const float*)d_in[6];  // [128]
    float* out = (float*)d_out;                       // [4,256,256]

    cudaFuncSetAttribute(k_attn4, cudaFuncAttributeMaxDynamicSharedMemorySize,
                         SMEM_ATTN);

    k_transpose<<<64, 256>>>(W_q, W_k);
    k_project<<<320, 256>>>(queries, keys);
    k_attn4<<<1024, 256, SMEM_ATTN>>>(values, valid_lens, w_v);
    k_combine<<<1024, 256>>>(valid_lens, out);
}